// round 13
// baseline (speedup 1.0000x reference)
#include <cuda_runtime.h>
#include <cuda_bf16.h>
#include <cuda_fp16.h>
#include <mma.h>
#include <math.h>

using namespace nvcuda;

#define USER_NUM 100000
#define ITEM_NUM 50000
#define NN 150000
#define NE 2400000
#define NBATCH 4096
#define SCAN_B ((NN + 255) / 256)   // 586

// Scratch (device globals; allocation is forbidden).
__device__ uint4 g_x16raw[150016 * 128 / 8];   // x * dis[row], fp16 (GEMM A)
__device__ uint4 g_h16raw[150016 * 128 / 8];   // hs = (x·dis)@W, fp16
__device__ uint4 g_w16raw[3 * 128 * 128 / 8];  // W0|W1|W2 fp16
#define G_X16 (reinterpret_cast<__half*>(g_x16raw))
#define G_H16 (reinterpret_cast<__half*>(g_h16raw))
#define G_W16 (reinterpret_cast<__half*>(g_w16raw))
__device__ float g_acc[150016 * 128];          // conv output (pre-BN, fp32)
__device__ float g_dis[150016];                // rsqrt(1+deg)
__device__ int   g_degi[150016];
__device__ int   g_rows[150016 + 16];          // CSR row offsets (by dst)
__device__ int   g_cursor[150016];
__device__ int   g_part[1024];
__device__ int   g_csrc[NE];                   // CSR column (src) ids
__device__ float g_stats[1024];                // L0: sum@0 sq@128 | L1: sum@512 sq@640
__device__ float g_loss;

// ---------------- setup ----------------

__global__ void k_zero() {
    int i = blockIdx.x * 256 + threadIdx.x;
    if (i < NN) g_degi[i] = 0;
    if (i < 256) { g_stats[i] = 0.f; g_stats[512 + i] = 0.f; }
    if (i == 0) g_loss = 0.f;
}

__global__ void k_deg(const int* __restrict__ dst) {
    int i = blockIdx.x * 256 + threadIdx.x;
    if (i >= NE / 4) return;
    int4 d = ((const int4*)dst)[i];
    atomicAdd(&g_degi[d.x], 1);
    atomicAdd(&g_degi[d.y], 1);
    atomicAdd(&g_degi[d.z], 1);
    atomicAdd(&g_degi[d.w], 1);
}

__global__ void k_dis() {
    int i = blockIdx.x * 256 + threadIdx.x;
    if (i < NN) g_dis[i] = rsqrtf(1.f + (float)g_degi[i]);
}

__global__ void k_concat16(const float* __restrict__ ue, const float* __restrict__ ie) {
    int i = blockIdx.x * 256 + threadIdx.x;
    const int TT = NN * 8;
    if (i >= TT) return;
    int row = i >> 3;
    int col = (i & 7) * 8;
    float d = g_dis[row];
    const float* srcp = (row < USER_NUM) ? ue + (size_t)row * 64 + col
                                         : ie + (size_t)(row - USER_NUM) * 64 + col;
    float4 v0 = *(const float4*)srcp;
    float4 v1 = *(const float4*)(srcp + 4);
    __align__(16) __half2 h[4];
    h[0] = __floats2half2_rn(v0.x * d, v0.y * d);
    h[1] = __floats2half2_rn(v0.z * d, v0.w * d);
    h[2] = __floats2half2_rn(v1.x * d, v1.y * d);
    h[3] = __floats2half2_rn(v1.z * d, v1.w * d);
    *reinterpret_cast<uint4*>(G_X16 + (size_t)row * 64 + col) =
        *reinterpret_cast<const uint4*>(h);
}

__global__ void k_wconv(const float* __restrict__ W, int kn4, int woff) {
    int i = blockIdx.x * 256 + threadIdx.x;
    if (i >= kn4) return;
    float4 v = ((const float4*)W)[i];
    __align__(8) __half2 h[2];
    h[0] = __floats2half2_rn(v.x, v.y);
    h[1] = __floats2half2_rn(v.z, v.w);
    *reinterpret_cast<uint2*>(G_W16 + woff + i * 4) = *reinterpret_cast<const uint2*>(h);
}

// ---------------- prefix scan ----------------

__global__ void k_scan1() {
    __shared__ int s[256];
    int tid = threadIdx.x;
    int i = blockIdx.x * 256 + tid;
    int v = (i < NN) ? g_degi[i] : 0;
    s[tid] = v;
    __syncthreads();
    for (int off = 1; off < 256; off <<= 1) {
        int t = (tid >= off) ? s[tid - off] : 0;
        __syncthreads();
        s[tid] += t;
        __syncthreads();
    }
    if (i < NN) g_rows[i] = s[tid] - v;
    if (tid == 255) g_part[blockIdx.x] = s[255];
}

__global__ void k_scan2() {  // 1 block, 1024 threads
    __shared__ int s[1024];
    int tid = threadIdx.x;
    int v = (tid < SCAN_B) ? g_part[tid] : 0;
    s[tid] = v;
    __syncthreads();
    for (int off = 1; off < 1024; off <<= 1) {
        int t = (tid >= off) ? s[tid - off] : 0;
        __syncthreads();
        s[tid] += t;
        __syncthreads();
    }
    if (tid < SCAN_B) g_part[tid] = s[tid] - v;
}

__global__ void k_scan3() {
    int i = blockIdx.x * 256 + threadIdx.x;
    if (i < NN) {
        int r = g_rows[i] + g_part[i >> 8];
        g_rows[i] = r;
        g_cursor[i] = r;
    }
    if (i == NN) g_rows[NN] = NE;
}

__global__ void k_csrfill(const int* __restrict__ src, const int* __restrict__ dst) {
    int i = blockIdx.x * 256 + threadIdx.x;
    if (i >= NE / 4) return;
    int4 s = ((const int4*)src)[i];
    int4 d = ((const int4*)dst)[i];
    g_csrc[atomicAdd(&g_cursor[d.x], 1)] = s.x;
    g_csrc[atomicAdd(&g_cursor[d.y], 1)] = s.y;
    g_csrc[atomicAdd(&g_cursor[d.z], 1)] = s.z;
    g_csrc[atomicAdd(&g_cursor[d.w], 1)] = s.w;
}

// ---------------- tensor-core GEMM: g_h16 = g_x16 @ W16 ----------------
template <int K, int N>
__global__ __launch_bounds__(256) void k_gemmh(int woff) {
    __shared__ __half Ws[K * N];
    __shared__ float scr[8][256];
    const int tid = threadIdx.x;
    const int wid = tid >> 5;
    const int lane = tid & 31;

    for (int i = tid; i < K * N / 8; i += 256)
        ((uint4*)Ws)[i] = ((const uint4*)(G_W16 + woff))[i];
    __syncthreads();

    const size_t rowbase = (size_t)blockIdx.x * 128 + wid * 16;
    const __half* A = G_X16 + rowbase * K;

    wmma::fragment<wmma::accumulator, 16, 16, 16, float> acc[N / 16];
#pragma unroll
    for (int j = 0; j < N / 16; j++) wmma::fill_fragment(acc[j], 0.f);

#pragma unroll
    for (int k0 = 0; k0 < K / 16; k0++) {
        wmma::fragment<wmma::matrix_a, 16, 16, 16, __half, wmma::row_major> a;
        wmma::load_matrix_sync(a, A + k0 * 16, K);
#pragma unroll
        for (int j = 0; j < N / 16; j++) {
            wmma::fragment<wmma::matrix_b, 16, 16, 16, __half, wmma::row_major> b;
            wmma::load_matrix_sync(b, Ws + k0 * 16 * N + j * 16, N);
            wmma::mma_sync(acc[j], a, b, acc[j]);
        }
    }

    __half* H = G_H16 + rowbase * N;
    const int r = lane >> 1;
    const int c0 = (lane & 1) * 8;
#pragma unroll
    for (int j = 0; j < N / 16; j++) {
        wmma::store_matrix_sync(scr[wid], acc[j], 16, wmma::mem_row_major);
        __syncwarp();
        __align__(16) __half2 h[4];
#pragma unroll
        for (int t = 0; t < 4; t++)
            h[t] = __floats2half2_rn(scr[wid][r * 16 + c0 + 2 * t],
                                     scr[wid][r * 16 + c0 + 2 * t + 1]);
        *reinterpret_cast<uint4*>(H + (size_t)r * N + j * 16 + c0) =
            *reinterpret_cast<const uint4*>(h);
        __syncwarp();
    }
}

// helper: accumulate 8 halves (uint4) into acc[8]
__device__ __forceinline__ void acc8(float* acc, uint4 r) {
    const __half2* hp = reinterpret_cast<const __half2*>(&r);
#pragma unroll
    for (int j = 0; j < 4; j++) {
        float2 f = __half22float2(hp[j]);
        acc[2 * j] += f.x;
        acc[2 * j + 1] += f.y;
    }
}

// ---------------- CSR aggregation, N=128 (mid layers, fused BN stats) ----------
// Warp = 2 groups of 16 lanes; each lane loads 16B (8 cols); groups stream
// edges with stride 2 -> 16 LDG.128 per edge instead of 32 LDG.64.
__global__ __launch_bounds__(256) void k_agg128(const float* __restrict__ b, int sbase) {
    const int lane = threadIdx.x & 31;
    const int warp = threadIdx.x >> 5;
    const int g = lane >> 4;       // group 0/1
    const int li = lane & 15;      // lane in group: owns cols li*8 .. li*8+7
    __shared__ float s_sum[128], s_sq[128];
    if (threadIdx.x < 128) { s_sum[threadIdx.x] = 0.f; s_sq[threadIdx.x] = 0.f; }
    __syncthreads();

    float bv[8], tsum[8], tsq[8];
#pragma unroll
    for (int i = 0; i < 8; i++) { bv[i] = b[li * 8 + i]; tsum[i] = 0.f; tsq[i] = 0.f; }

    for (int node = blockIdx.x * 8 + warp; node < NN; node += gridDim.x * 8) {
        float acc[8];
#pragma unroll
        for (int i = 0; i < 8; i++) acc[i] = 0.f;
        if (g == 0) {  // self row, counted once
            uint4 r = *(const uint4*)(G_H16 + (size_t)node * 128 + li * 8);
            acc8(acc, r);
        }
        int beg = g_rows[node], end = g_rows[node + 1];
        int e = beg + g;
        for (; e + 2 < end; e += 4) {  // 2-unroll per group -> 4 loads in flight/warp
            int s0 = g_csrc[e], s1 = g_csrc[e + 2];
            uint4 r0 = *(const uint4*)(G_H16 + (size_t)s0 * 128 + li * 8);
            uint4 r1 = *(const uint4*)(G_H16 + (size_t)s1 * 128 + li * 8);
            acc8(acc, r0);
            acc8(acc, r1);
        }
        if (e < end) {
            int s0 = g_csrc[e];
            uint4 r0 = *(const uint4*)(G_H16 + (size_t)s0 * 128 + li * 8);
            acc8(acc, r0);
        }
        // combine the two groups (lane li <-> lane li+16 hold same columns)
#pragma unroll
        for (int i = 0; i < 8; i++) acc[i] += __shfl_xor_sync(0xffffffffu, acc[i], 16);

        if (g == 0) {
            float dd = g_dis[node];
            float v[8];
#pragma unroll
            for (int i = 0; i < 8; i++) {
                v[i] = fmaf(acc[i], dd, bv[i]);
                tsum[i] += v[i];
                tsq[i] += v[i] * v[i];
            }
            float* orow = g_acc + (size_t)node * 128 + li * 8;
            *(float4*)orow = make_float4(v[0], v[1], v[2], v[3]);
            *(float4*)(orow + 4) = make_float4(v[4], v[5], v[6], v[7]);
        }
    }

    if ((threadIdx.x & 16) == 0) {  // group-0 lanes only
#pragma unroll
        for (int i = 0; i < 8; i++) {
            atomicAdd(&s_sum[li * 8 + i], tsum[i]);
            atomicAdd(&s_sq[li * 8 + i], tsq[i]);
        }
    }
    __syncthreads();
    if (threadIdx.x < 128) {
        atomicAdd(&g_stats[sbase + threadIdx.x], s_sum[threadIdx.x]);
        atomicAdd(&g_stats[sbase + 128 + threadIdx.x], s_sq[threadIdx.x]);
    }
}

// ---------------- CSR aggregation, N=64 (final layer -> unaligned out) --------
// Warp = 4 groups of 8 lanes; 8 LDG.128 per edge, 4 edges concurrent.
__global__ __launch_bounds__(256) void k_agg64(const float* __restrict__ b,
                                               float* __restrict__ out) {
    const int lane = threadIdx.x & 31;
    const int warp = threadIdx.x >> 5;
    const int g = lane >> 3;       // group 0..3
    const int li = lane & 7;       // owns cols li*8 .. li*8+7
    float bv[8];
#pragma unroll
    for (int i = 0; i < 8; i++) bv[i] = b[li * 8 + i];

    for (int node = blockIdx.x * 8 + warp; node < NN; node += gridDim.x * 8) {
        float acc[8];
#pragma unroll
        for (int i = 0; i < 8; i++) acc[i] = 0.f;
        if (g == 0) {
            uint4 r = *(const uint4*)(G_H16 + (size_t)node * 64 + li * 8);
            acc8(acc, r);
        }
        int beg = g_rows[node], end = g_rows[node + 1];
        int e = beg + g;
        for (; e + 4 < end; e += 8) {  // 2-unroll per group -> 8 loads in flight/warp
            int s0 = g_csrc[e], s1 = g_csrc[e + 4];
            uint4 r0 = *(const uint4*)(G_H16 + (size_t)s0 * 64 + li * 8);
            uint4 r1 = *(const uint4*)(G_H16 + (size_t)s1 * 64 + li * 8);
            acc8(acc, r0);
            acc8(acc, r1);
        }
        if (e < end) {
            int s0 = g_csrc[e];
            uint4 r0 = *(const uint4*)(G_H16 + (size_t)s0 * 64 + li * 8);
            acc8(acc, r0);
        }
#pragma unroll
        for (int i = 0; i < 8; i++) {
            acc[i] += __shfl_xor_sync(0xffffffffu, acc[i], 8);
            acc[i] += __shfl_xor_sync(0xffffffffu, acc[i], 16);
        }
        if (g == 0) {
            float dd = g_dis[node];
            float* orow = out + (size_t)node * 64 + li * 8;
#pragma unroll
            for (int i = 0; i < 8; i++) orow[i] = fmaf(acc[i], dd, bv[i]);
        }
    }
}

// ---------------- BN apply (stats->scale/shift in-block) + ReLU + L2 + fp16 ----
__global__ __launch_bounds__(256) void k_bnapply(const float* __restrict__ g,
                                                 const float* __restrict__ beta,
                                                 int sbase) {
    __shared__ float s_sc[128], s_sh[128];
    if (threadIdx.x < 128) {
        int c = threadIdx.x;
        float m = g_stats[sbase + c] * (1.f / NN);
        float var = g_stats[sbase + 128 + c] * (1.f / NN) - m * m;
        float sc = g[c] * rsqrtf(var + 1e-5f);
        s_sc[c] = sc;
        s_sh[c] = beta[c] - m * sc;
    }
    __syncthreads();
    int row = blockIdx.x * 8 + (threadIdx.x >> 5);
    int lane = threadIdx.x & 31;
    if (row >= NN) return;
    float4 v = *reinterpret_cast<const float4*>(g_acc + (size_t)row * 128 + lane * 4);
    float4 sc = *reinterpret_cast<const float4*>(s_sc + lane * 4);
    float4 sh = *reinterpret_cast<const float4*>(s_sh + lane * 4);
    float y0 = fmaxf(fmaf(v.x, sc.x, sh.x), 0.f);
    float y1 = fmaxf(fmaf(v.y, sc.y, sh.y), 0.f);
    float y2 = fmaxf(fmaf(v.z, sc.z, sh.z), 0.f);
    float y3 = fmaxf(fmaf(v.w, sc.w, sh.w), 0.f);
    float sq = y0 * y0 + y1 * y1 + y2 * y2 + y3 * y3;
#pragma unroll
    for (int o = 16; o; o >>= 1) sq += __shfl_xor_sync(0xffffffffu, sq, o);
    float inv = 1.f / fmaxf(sqrtf(sq), 1e-12f);
    inv *= g_dis[row];  // pre-scale for next GEMM
    __align__(8) __half2 h[2];
    h[0] = __floats2half2_rn(y0 * inv, y1 * inv);
    h[1] = __floats2half2_rn(y2 * inv, y3 * inv);
    *reinterpret_cast<uint2*>(G_X16 + (size_t)row * 128 + lane * 4) =
        *reinterpret_cast<const uint2*>(h);
}

// ---------------- BPR loss ----------------
__global__ __launch_bounds__(256) void k_loss(const float* __restrict__ xo,
                                              const int* __restrict__ uid,
                                              const int* __restrict__ pid,
                                              const int* __restrict__ nid) {
    int s = blockIdx.x * 8 + (threadIdx.x >> 5);
    int lane = threadIdx.x & 31;
    if (s >= NBATCH) return;
    const float* u = xo + (size_t)uid[s] * 64;
    const float* p = xo + (size_t)(USER_NUM + pid[s]) * 64;
    const float* nr = xo + (size_t)(USER_NUM + nid[s]) * 64;
    float ps = 0.f, ns = 0.f;
#pragma unroll
    for (int j = 0; j < 2; j++) {
        int c = lane + j * 32;
        float uv = u[c];
        ps += uv * p[c];
        ns += uv * nr[c];
    }
#pragma unroll
    for (int o = 16; o; o >>= 1) {
        ps += __shfl_xor_sync(0xffffffffu, ps, o);
        ns += __shfl_xor_sync(0xffffffffu, ns, o);
    }
    if (lane == 0) {
        float z = ps - ns;
        float ls = fminf(z, 0.f) - log1pf(expf(-fabsf(z)));
        atomicAdd(&g_loss, ls);
    }
}

__global__ void k_wloss(float* __restrict__ out) {
    out[0] = -g_loss * (1.f / NBATCH);
}

// ---------------- launch ----------------
extern "C" void kernel_launch(void* const* d_in, const int* in_sizes, int n_in,
                              void* d_out, int out_size) {
    const float* user_emb = (const float*)d_in[0];
    const float* item_emb = (const float*)d_in[1];
    const float* W0 = (const float*)d_in[2];
    const float* b0 = (const float*)d_in[3];
    const float* g0 = (const float*)d_in[4];
    const float* beta0 = (const float*)d_in[5];
    const float* W1 = (const float*)d_in[6];
    const float* b1 = (const float*)d_in[7];
    const float* g1 = (const float*)d_in[8];
    const float* beta1 = (const float*)d_in[9];
    const float* W2 = (const float*)d_in[10];
    const float* b2 = (const float*)d_in[11];
    const int* user_id = (const int*)d_in[12];
    const int* pos_item = (const int*)d_in[13];
    const int* neg_item = (const int*)d_in[14];
    const int* ei = (const int*)d_in[15];
    const int* src = ei;
    const int* dst = ei + NE;

    float* out = (float*)d_out;
    float* xout = out + 1;  // [rec_loss, x(150000x64)] -- only 4B aligned!

    const int EB4 = (NE / 4 + 255) / 256;
    const int AGGB = 2048;
    const int GB = (NN + 127) / 128;  // 1172
    const int W64 = 64 * 128 / 4, W128 = 128 * 128 / 4, W64b = 128 * 64 / 4;

    // setup + CSR build
    k_zero<<<(NN + 255) / 256, 256>>>();
    k_wconv<<<(W64 + 255) / 256, 256>>>(W0, W64, 0);
    k_wconv<<<(W128 + 255) / 256, 256>>>(W1, W128, 128 * 128);
    k_wconv<<<(W64b + 255) / 256, 256>>>(W2, W64b, 2 * 128 * 128);
    k_deg<<<EB4, 256>>>(dst);
    k_dis<<<(NN + 255) / 256, 256>>>();
    k_concat16<<<(NN * 8 + 255) / 256, 256>>>(user_emb, item_emb);
    k_scan1<<<SCAN_B, 256>>>();
    k_scan2<<<1, 1024>>>();
    k_scan3<<<SCAN_B + 1, 256>>>();
    k_csrfill<<<EB4, 256>>>(src, dst);

    // ---- layer 0: 64 -> 128 ----
    k_gemmh<64, 128><<<GB, 256>>>(0);
    k_agg128<<<AGGB, 256>>>(b0, 0);
    k_bnapply<<<(NN + 7) / 8, 256>>>(g0, beta0, 0);

    // ---- layer 1: 128 -> 128 ----
    k_gemmh<128, 128><<<GB, 256>>>(128 * 128);
    k_agg128<<<AGGB, 256>>>(b1, 512);
    k_bnapply<<<(NN + 7) / 8, 256>>>(g1, beta1, 512);

    // ---- layer 2: 128 -> 64 ----
    k_gemmh<128, 64><<<GB, 256>>>(2 * 128 * 128);
    k_agg64<<<AGGB, 256>>>(b2, xout);

    // ---- loss ----
    k_loss<<<(NBATCH + 7) / 8, 256>>>(xout, user_id, pos_item, neg_item);
    k_wloss<<<1, 1>>>(out);
}

// round 14
// speedup vs baseline: 1.1216x; 1.1216x over previous
#include <cuda_runtime.h>
#include <cuda_bf16.h>
#include <cuda_fp16.h>
#include <mma.h>
#include <math.h>

using namespace nvcuda;

#define USER_NUM 100000
#define ITEM_NUM 50000
#define NN 150000
#define NE 2400000
#define NBATCH 4096
#define SCAN_B ((NN + 255) / 256)   // 586

// Scratch (device globals; allocation is forbidden).
__device__ uint4 g_x16raw[150016 * 128 / 8];   // x * dis[row], fp16 (GEMM A)
__device__ uint4 g_h16raw[150016 * 128 / 8];   // hs = (x·dis)@W, fp16
__device__ uint4 g_w16raw[3 * 128 * 128 / 8];  // W0|W1|W2 fp16
#define G_X16 (reinterpret_cast<__half*>(g_x16raw))
#define G_H16 (reinterpret_cast<__half*>(g_h16raw))
#define G_W16 (reinterpret_cast<__half*>(g_w16raw))
__device__ uint2 g_a16raw[150016 * 128 / 4];   // conv output (pre-BN), fp16
#define G_A16 (reinterpret_cast<__half*>(g_a16raw))
__device__ float g_dis[150016];                // rsqrt(1+deg)
__device__ int   g_degi[150016];
__device__ int   g_rows[150016 + 16];          // CSR row offsets (by dst)
__device__ int   g_cursor[150016];
__device__ int   g_part[1024];
__device__ int   g_csrc[NE];                   // CSR column (src) ids
__device__ float g_stats[1024];                // L0: sum@0 sq@128 | L1: sum@512 sq@640
__device__ float g_loss;

// ---------------- setup ----------------

__global__ void k_zero() {
    int i = blockIdx.x * 256 + threadIdx.x;
    if (i < NN) g_degi[i] = 0;
    if (i < 256) { g_stats[i] = 0.f; g_stats[512 + i] = 0.f; }
    if (i == 0) g_loss = 0.f;
}

__global__ void k_deg(const int* __restrict__ dst) {
    int i = blockIdx.x * 256 + threadIdx.x;
    if (i >= NE / 4) return;
    int4 d = ((const int4*)dst)[i];
    atomicAdd(&g_degi[d.x], 1);
    atomicAdd(&g_degi[d.y], 1);
    atomicAdd(&g_degi[d.z], 1);
    atomicAdd(&g_degi[d.w], 1);
}

__global__ void k_dis() {
    int i = blockIdx.x * 256 + threadIdx.x;
    if (i < NN) g_dis[i] = rsqrtf(1.f + (float)g_degi[i]);
}

__global__ void k_concat16(const float* __restrict__ ue, const float* __restrict__ ie) {
    int i = blockIdx.x * 256 + threadIdx.x;
    const int TT = NN * 8;
    if (i >= TT) return;
    int row = i >> 3;
    int col = (i & 7) * 8;
    float d = g_dis[row];
    const float* srcp = (row < USER_NUM) ? ue + (size_t)row * 64 + col
                                         : ie + (size_t)(row - USER_NUM) * 64 + col;
    float4 v0 = *(const float4*)srcp;
    float4 v1 = *(const float4*)(srcp + 4);
    __align__(16) __half2 h[4];
    h[0] = __floats2half2_rn(v0.x * d, v0.y * d);
    h[1] = __floats2half2_rn(v0.z * d, v0.w * d);
    h[2] = __floats2half2_rn(v1.x * d, v1.y * d);
    h[3] = __floats2half2_rn(v1.z * d, v1.w * d);
    *reinterpret_cast<uint4*>(G_X16 + (size_t)row * 64 + col) =
        *reinterpret_cast<const uint4*>(h);
}

__global__ void k_wconv(const float* __restrict__ W, int kn4, int woff) {
    int i = blockIdx.x * 256 + threadIdx.x;
    if (i >= kn4) return;
    float4 v = ((const float4*)W)[i];
    __align__(8) __half2 h[2];
    h[0] = __floats2half2_rn(v.x, v.y);
    h[1] = __floats2half2_rn(v.z, v.w);
    *reinterpret_cast<uint2*>(G_W16 + woff + i * 4) = *reinterpret_cast<const uint2*>(h);
}

// ---------------- prefix scan ----------------

__global__ void k_scan1() {
    __shared__ int s[256];
    int tid = threadIdx.x;
    int i = blockIdx.x * 256 + tid;
    int v = (i < NN) ? g_degi[i] : 0;
    s[tid] = v;
    __syncthreads();
    for (int off = 1; off < 256; off <<= 1) {
        int t = (tid >= off) ? s[tid - off] : 0;
        __syncthreads();
        s[tid] += t;
        __syncthreads();
    }
    if (i < NN) g_rows[i] = s[tid] - v;
    if (tid == 255) g_part[blockIdx.x] = s[255];
}

__global__ void k_scan2() {  // 1 block, 1024 threads
    __shared__ int s[1024];
    int tid = threadIdx.x;
    int v = (tid < SCAN_B) ? g_part[tid] : 0;
    s[tid] = v;
    __syncthreads();
    for (int off = 1; off < 1024; off <<= 1) {
        int t = (tid >= off) ? s[tid - off] : 0;
        __syncthreads();
        s[tid] += t;
        __syncthreads();
    }
    if (tid < SCAN_B) g_part[tid] = s[tid] - v;
}

__global__ void k_scan3() {
    int i = blockIdx.x * 256 + threadIdx.x;
    if (i < NN) {
        int r = g_rows[i] + g_part[i >> 8];
        g_rows[i] = r;
        g_cursor[i] = r;
    }
    if (i == NN) g_rows[NN] = NE;
}

__global__ void k_csrfill(const int* __restrict__ src, const int* __restrict__ dst) {
    int i = blockIdx.x * 256 + threadIdx.x;
    if (i >= NE / 4) return;
    int4 s = ((const int4*)src)[i];
    int4 d = ((const int4*)dst)[i];
    g_csrc[atomicAdd(&g_cursor[d.x], 1)] = s.x;
    g_csrc[atomicAdd(&g_cursor[d.y], 1)] = s.y;
    g_csrc[atomicAdd(&g_cursor[d.z], 1)] = s.z;
    g_csrc[atomicAdd(&g_cursor[d.w], 1)] = s.w;
}

// ---------------- tensor-core GEMM: g_h16 = g_x16 @ W16 ----------------
template <int K, int N>
__global__ __launch_bounds__(256) void k_gemmh(int woff) {
    __shared__ __half Ws[K * N];
    __shared__ float scr[8][256];
    const int tid = threadIdx.x;
    const int wid = tid >> 5;
    const int lane = tid & 31;

    for (int i = tid; i < K * N / 8; i += 256)
        ((uint4*)Ws)[i] = ((const uint4*)(G_W16 + woff))[i];
    __syncthreads();

    const size_t rowbase = (size_t)blockIdx.x * 128 + wid * 16;
    const __half* A = G_X16 + rowbase * K;

    wmma::fragment<wmma::accumulator, 16, 16, 16, float> acc[N / 16];
#pragma unroll
    for (int j = 0; j < N / 16; j++) wmma::fill_fragment(acc[j], 0.f);

#pragma unroll
    for (int k0 = 0; k0 < K / 16; k0++) {
        wmma::fragment<wmma::matrix_a, 16, 16, 16, __half, wmma::row_major> a;
        wmma::load_matrix_sync(a, A + k0 * 16, K);
#pragma unroll
        for (int j = 0; j < N / 16; j++) {
            wmma::fragment<wmma::matrix_b, 16, 16, 16, __half, wmma::row_major> b;
            wmma::load_matrix_sync(b, Ws + k0 * 16 * N + j * 16, N);
            wmma::mma_sync(acc[j], a, b, acc[j]);
        }
    }

    __half* H = G_H16 + rowbase * N;
    const int r = lane >> 1;
    const int c0 = (lane & 1) * 8;
#pragma unroll
    for (int j = 0; j < N / 16; j++) {
        wmma::store_matrix_sync(scr[wid], acc[j], 16, wmma::mem_row_major);
        __syncwarp();
        __align__(16) __half2 h[4];
#pragma unroll
        for (int t = 0; t < 4; t++)
            h[t] = __floats2half2_rn(scr[wid][r * 16 + c0 + 2 * t],
                                     scr[wid][r * 16 + c0 + 2 * t + 1]);
        *reinterpret_cast<uint4*>(H + (size_t)r * N + j * 16 + c0) =
            *reinterpret_cast<const uint4*>(h);
        __syncwarp();
    }
}

// ---------------- CSR aggregation (warp-per-node, U=8 unroll) ----------------
// v[n] = dis[n]*(h[n] + sum_{e->n} h[src_e]) + b; h fp16, accum fp32.
// FINAL=false: writes fp16 to G_A16, accumulates BN column stats.
// FINAL=true : writes fp32 scalars to harness `out` (4B-aligned).
template <int N, bool FINAL>
__global__ __launch_bounds__(256) void k_agg(const float* __restrict__ b,
                                             float* __restrict__ out, int sbase) {
    constexpr int VE = N / 32;  // 4 or 2 halves per lane
    const int lane = threadIdx.x & 31;
    const int warp = threadIdx.x >> 5;
    __shared__ float s_sum[128], s_sq[128];
    if constexpr (!FINAL) {
        if (threadIdx.x < 128) { s_sum[threadIdx.x] = 0.f; s_sq[threadIdx.x] = 0.f; }
        __syncthreads();
    }
    float bv[VE], tsum[VE], tsq[VE];
#pragma unroll
    for (int i = 0; i < VE; i++) { bv[i] = b[lane * VE + i]; tsum[i] = 0.f; tsq[i] = 0.f; }

    for (int node = blockIdx.x * 8 + warp; node < NN; node += gridDim.x * 8) {
        float acc[VE];
        // self row
        if constexpr (VE == 4) {
            uint2 raw = *(const uint2*)(G_H16 + (size_t)node * N + lane * 4);
            float2 f0 = __half22float2(*reinterpret_cast<__half2*>(&raw.x));
            float2 f1 = __half22float2(*reinterpret_cast<__half2*>(&raw.y));
            acc[0] = f0.x; acc[1] = f0.y; acc[2] = f1.x; acc[3] = f1.y;
        } else {
            unsigned raw = *(const unsigned*)(G_H16 + (size_t)node * N + lane * 2);
            float2 f = __half22float2(*reinterpret_cast<__half2*>(&raw));
            acc[0] = f.x; acc[1] = f.y;
        }
        int beg = g_rows[node], end = g_rows[node + 1];
        int e = beg;
        // U=8: 8 independent row loads in flight
        for (; e + 8 <= end; e += 8) {
            int sid[8];
#pragma unroll
            for (int u = 0; u < 8; u++) sid[u] = g_csrc[e + u];
            if constexpr (VE == 4) {
                uint2 r[8];
#pragma unroll
                for (int u = 0; u < 8; u++)
                    r[u] = *(const uint2*)(G_H16 + (size_t)sid[u] * N + lane * 4);
#pragma unroll
                for (int u = 0; u < 8; u++) {
                    float2 f0 = __half22float2(*reinterpret_cast<__half2*>(&r[u].x));
                    float2 f1 = __half22float2(*reinterpret_cast<__half2*>(&r[u].y));
                    acc[0] += f0.x; acc[1] += f0.y; acc[2] += f1.x; acc[3] += f1.y;
                }
            } else {
                unsigned r[8];
#pragma unroll
                for (int u = 0; u < 8; u++)
                    r[u] = *(const unsigned*)(G_H16 + (size_t)sid[u] * N + lane * 2);
#pragma unroll
                for (int u = 0; u < 8; u++) {
                    float2 f = __half22float2(*reinterpret_cast<__half2*>(&r[u]));
                    acc[0] += f.x; acc[1] += f.y;
                }
            }
        }
        for (; e < end; e++) {
            int s0 = g_csrc[e];
            if constexpr (VE == 4) {
                uint2 r0 = *(const uint2*)(G_H16 + (size_t)s0 * N + lane * 4);
                float2 f0 = __half22float2(*reinterpret_cast<__half2*>(&r0.x));
                float2 f1 = __half22float2(*reinterpret_cast<__half2*>(&r0.y));
                acc[0] += f0.x; acc[1] += f0.y; acc[2] += f1.x; acc[3] += f1.y;
            } else {
                unsigned r0 = *(const unsigned*)(G_H16 + (size_t)s0 * N + lane * 2);
                float2 f = __half22float2(*reinterpret_cast<__half2*>(&r0));
                acc[0] += f.x; acc[1] += f.y;
            }
        }
        float dd = g_dis[node];
        float v[VE];
#pragma unroll
        for (int i = 0; i < VE; i++) {
            v[i] = fmaf(acc[i], dd, bv[i]);
            if constexpr (!FINAL) { tsum[i] += v[i]; tsq[i] += v[i] * v[i]; }
        }

        if constexpr (FINAL) {
            float* orow = out + (size_t)node * N + lane * VE;
#pragma unroll
            for (int i = 0; i < VE; i++) orow[i] = v[i];
        } else {
            __align__(8) __half2 h[2];
            h[0] = __floats2half2_rn(v[0], v[1]);
            h[1] = __floats2half2_rn(v[2], v[3]);
            *reinterpret_cast<uint2*>(G_A16 + (size_t)node * 128 + lane * 4) =
                *reinterpret_cast<const uint2*>(h);
        }
    }

    if constexpr (!FINAL) {
#pragma unroll
        for (int i = 0; i < VE; i++) {
            atomicAdd(&s_sum[lane * VE + i], tsum[i]);
            atomicAdd(&s_sq[lane * VE + i], tsq[i]);
        }
        __syncthreads();
        if (threadIdx.x < 128) {
            atomicAdd(&g_stats[sbase + threadIdx.x], s_sum[threadIdx.x]);
            atomicAdd(&g_stats[sbase + 128 + threadIdx.x], s_sq[threadIdx.x]);
        }
    }
}

// ---------------- BN apply (stats->scale/shift in-block) + ReLU + L2 + fp16 ----
__global__ __launch_bounds__(256) void k_bnapply(const float* __restrict__ g,
                                                 const float* __restrict__ beta,
                                                 int sbase) {
    __shared__ float s_sc[128], s_sh[128];
    if (threadIdx.x < 128) {
        int c = threadIdx.x;
        float m = g_stats[sbase + c] * (1.f / NN);
        float var = g_stats[sbase + 128 + c] * (1.f / NN) - m * m;
        float sc = g[c] * rsqrtf(var + 1e-5f);
        s_sc[c] = sc;
        s_sh[c] = beta[c] - m * sc;
    }
    __syncthreads();
    int row = blockIdx.x * 8 + (threadIdx.x >> 5);
    int lane = threadIdx.x & 31;
    if (row >= NN) return;
    uint2 raw = *reinterpret_cast<const uint2*>(G_A16 + (size_t)row * 128 + lane * 4);
    float2 f0 = __half22float2(*reinterpret_cast<__half2*>(&raw.x));
    float2 f1 = __half22float2(*reinterpret_cast<__half2*>(&raw.y));
    float4 sc = *reinterpret_cast<const float4*>(s_sc + lane * 4);
    float4 sh = *reinterpret_cast<const float4*>(s_sh + lane * 4);
    float y0 = fmaxf(fmaf(f0.x, sc.x, sh.x), 0.f);
    float y1 = fmaxf(fmaf(f0.y, sc.y, sh.y), 0.f);
    float y2 = fmaxf(fmaf(f1.x, sc.z, sh.z), 0.f);
    float y3 = fmaxf(fmaf(f1.y, sc.w, sh.w), 0.f);
    float sq = y0 * y0 + y1 * y1 + y2 * y2 + y3 * y3;
#pragma unroll
    for (int o = 16; o; o >>= 1) sq += __shfl_xor_sync(0xffffffffu, sq, o);
    float inv = 1.f / fmaxf(sqrtf(sq), 1e-12f);
    inv *= g_dis[row];  // pre-scale for next GEMM
    __align__(8) __half2 h[2];
    h[0] = __floats2half2_rn(y0 * inv, y1 * inv);
    h[1] = __floats2half2_rn(y2 * inv, y3 * inv);
    *reinterpret_cast<uint2*>(G_X16 + (size_t)row * 128 + lane * 4) =
        *reinterpret_cast<const uint2*>(h);
}

// ---------------- BPR loss ----------------
__global__ __launch_bounds__(256) void k_loss(const float* __restrict__ xo,
                                              const int* __restrict__ uid,
                                              const int* __restrict__ pid,
                                              const int* __restrict__ nid) {
    int s = blockIdx.x * 8 + (threadIdx.x >> 5);
    int lane = threadIdx.x & 31;
    if (s >= NBATCH) return;
    const float* u = xo + (size_t)uid[s] * 64;
    const float* p = xo + (size_t)(USER_NUM + pid[s]) * 64;
    const float* nr = xo + (size_t)(USER_NUM + nid[s]) * 64;
    float ps = 0.f, ns = 0.f;
#pragma unroll
    for (int j = 0; j < 2; j++) {
        int c = lane + j * 32;
        float uv = u[c];
        ps += uv * p[c];
        ns += uv * nr[c];
    }
#pragma unroll
    for (int o = 16; o; o >>= 1) {
        ps += __shfl_xor_sync(0xffffffffu, ps, o);
        ns += __shfl_xor_sync(0xffffffffu, ns, o);
    }
    if (lane == 0) {
        float z = ps - ns;
        float ls = fminf(z, 0.f) - log1pf(expf(-fabsf(z)));
        atomicAdd(&g_loss, ls);
    }
}

__global__ void k_wloss(float* __restrict__ out) {
    out[0] = -g_loss * (1.f / NBATCH);
}

// ---------------- launch ----------------
extern "C" void kernel_launch(void* const* d_in, const int* in_sizes, int n_in,
                              void* d_out, int out_size) {
    const float* user_emb = (const float*)d_in[0];
    const float* item_emb = (const float*)d_in[1];
    const float* W0 = (const float*)d_in[2];
    const float* b0 = (const float*)d_in[3];
    const float* g0 = (const float*)d_in[4];
    const float* beta0 = (const float*)d_in[5];
    const float* W1 = (const float*)d_in[6];
    const float* b1 = (const float*)d_in[7];
    const float* g1 = (const float*)d_in[8];
    const float* beta1 = (const float*)d_in[9];
    const float* W2 = (const float*)d_in[10];
    const float* b2 = (const float*)d_in[11];
    const int* user_id = (const int*)d_in[12];
    const int* pos_item = (const int*)d_in[13];
    const int* neg_item = (const int*)d_in[14];
    const int* ei = (const int*)d_in[15];
    const int* src = ei;
    const int* dst = ei + NE;

    float* out = (float*)d_out;
    float* xout = out + 1;  // [rec_loss, x(150000x64)] -- only 4B aligned!

    const int EB4 = (NE / 4 + 255) / 256;
    const int AGGB = 2048;
    const int GB = (NN + 127) / 128;  // 1172
    const int W64 = 64 * 128 / 4, W128 = 128 * 128 / 4, W64b = 128 * 64 / 4;

    // setup + CSR build
    k_zero<<<(NN + 255) / 256, 256>>>();
    k_wconv<<<(W64 + 255) / 256, 256>>>(W0, W64, 0);
    k_wconv<<<(W128 + 255) / 256, 256>>>(W1, W128, 128 * 128);
    k_wconv<<<(W64b + 255) / 256, 256>>>(W2, W64b, 2 * 128 * 128);
    k_deg<<<EB4, 256>>>(dst);
    k_dis<<<(NN + 255) / 256, 256>>>();
    k_concat16<<<(NN * 8 + 255) / 256, 256>>>(user_emb, item_emb);
    k_scan1<<<SCAN_B, 256>>>();
    k_scan2<<<1, 1024>>>();
    k_scan3<<<SCAN_B + 1, 256>>>();
    k_csrfill<<<EB4, 256>>>(src, dst);

    // ---- layer 0: 64 -> 128 ----
    k_gemmh<64, 128><<<GB, 256>>>(0);
    k_agg<128, false><<<AGGB, 256>>>(b0, nullptr, 0);
    k_bnapply<<<(NN + 7) / 8, 256>>>(g0, beta0, 0);

    // ---- layer 1: 128 -> 128 ----
    k_gemmh<128, 128><<<GB, 256>>>(128 * 128);
    k_agg<128, false><<<AGGB, 256>>>(b1, nullptr, 512);
    k_bnapply<<<(NN + 7) / 8, 256>>>(g1, beta1, 512);

    // ---- layer 2: 128 -> 64 ----
    k_gemmh<128, 64><<<GB, 256>>>(2 * 128 * 128);
    k_agg<64, true><<<AGGB, 256>>>(b2, xout, 0);

    // ---- loss ----
    k_loss<<<(NBATCH + 7) / 8, 256>>>(xout, user_id, pos_item, neg_item);
    k_wloss<<<1, 1>>>(out);
}